// round 7
// baseline (speedup 1.0000x reference)
#include <cuda_runtime.h>
#include <cuda_fp16.h>
#include <stdint.h>

#define T_STEPS 1024
#define BATCH   128
#define INDIM   6
#define HDIM    1536
#define OUTDIM  5
#define WELEMS  (4*HDIM*HDIM)     // 9437184

#define NCTA     128
#define NC       12               // h-columns per CTA
#define NLOC     48               // gate rows per CTA (4*NC)
#define NTHREADS 512

#define KC       128              // halfs per K stage (256 B rows = 2 SW128 atoms)
#define RB       256              // row bytes
#define NCHUNK   (HDIM/KC)        // 12 stages per 1536-K GEMM
#define NSTAGE   4
#define A_BYTES  (128*RB)         // 32768
#define B_BYTES  (NLOC*RB)        // 12288
#define STAGE_BYTES (A_BYTES + B_BYTES)        // 45056
#define OFF_GATES   (NSTAGE*STAGE_BYTES)       // 180224 (float[128*48] = 24576)
#define OFF_WX      (OFF_GATES + 128*NLOC*4)   // 204800
#define OFF_B0      (OFF_WX + NLOC*INDIM*4)
#define OFF_B1      (OFF_B0 + NLOC*4)
#define SMEM_DYN    (OFF_B1 + NLOC*4 + 256)    // ~206.6 KB

#define NE 3                      // state elements per thread (1536/512)

// ---------------- device globals ---------------------------------------------
__device__ __align__(128) __half g_Whh0[WELEMS];
__device__ __align__(128) __half g_Wih1[WELEMS];
__device__ __align__(128) __half g_Whh1[WELEMS];
__device__ __align__(128) __half g_h0[2][BATCH*HDIM];
__device__ __align__(128) __half g_h1[2][BATCH*HDIM];
__device__ __align__(128) float  g_h1f[BATCH*HDIM];
__device__ unsigned g_bar;

// ---------------- weight convert + barrier reset -----------------------------
__global__ void convert_kernel(const float* __restrict__ whh0,
                               const float* __restrict__ wih1,
                               const float* __restrict__ whh1) {
    long i = (long)blockIdx.x * blockDim.x + threadIdx.x;
    if (i == 0) g_bar = 0u;
    if (i < (long)WELEMS)            g_Whh0[i]             = __float2half_rn(whh0[i]);
    else if (i < 2L*WELEMS)          g_Wih1[i - WELEMS]    = __float2half_rn(wih1[i - WELEMS]);
    else if (i < 3L*WELEMS)          g_Whh1[i - 2L*WELEMS] = __float2half_rn(whh1[i - 2L*WELEMS]);
}

// ---------------- PTX helpers -------------------------------------------------
__device__ __forceinline__ void cpa16(uint32_t s, const void* g) {
    asm volatile("cp.async.cg.shared.global [%0], [%1], 16;\n" :: "r"(s), "l"(g) : "memory");
}
__device__ __forceinline__ void cp_commit() { asm volatile("cp.async.commit_group;\n" ::: "memory"); }
__device__ __forceinline__ void cp_waitp()  { asm volatile("cp.async.wait_group %0;\n" :: "n"(NSTAGE-2) : "memory"); }

__device__ __forceinline__ void ldsm_x4(uint32_t* r, uint32_t addr) {
    asm volatile("ldmatrix.sync.aligned.m8n8.x4.shared.b16 {%0,%1,%2,%3}, [%4];\n"
                 : "=r"(r[0]), "=r"(r[1]), "=r"(r[2]), "=r"(r[3]) : "r"(addr));
}
__device__ __forceinline__ void ldsm_x2(uint32_t* r, uint32_t addr) {
    asm volatile("ldmatrix.sync.aligned.m8n8.x2.shared.b16 {%0,%1}, [%2];\n"
                 : "=r"(r[0]), "=r"(r[1]) : "r"(addr));
}
__device__ __forceinline__ void mma16816(float* d, const uint32_t* a, uint32_t b0, uint32_t b1) {
    asm volatile(
        "mma.sync.aligned.m16n8k16.row.col.f32.f16.f16.f32 "
        "{%0,%1,%2,%3}, {%4,%5,%6,%7}, {%8,%9}, {%0,%1,%2,%3};\n"
        : "+f"(d[0]), "+f"(d[1]), "+f"(d[2]), "+f"(d[3])
        : "r"(a[0]), "r"(a[1]), "r"(a[2]), "r"(a[3]), "r"(b0), "r"(b1));
}

__device__ __forceinline__ float sigm(float x)  { return __fdividef(1.0f, 1.0f + __expf(-x)); }
__device__ __forceinline__ float tanh_f(float x){ return __fdividef(2.0f, 1.0f + __expf(-2.0f*x)) - 1.0f; }

// ---------------- per-thread precomputed context ------------------------------
struct Ctx {
    uint32_t offA;           // A row-base byte offset within a stage
    uint32_t offB4, offB2;   // B row-base byte offsets (x4 tiles, x2 tile)
    uint32_t cq4[8], cq2[8]; // per-k16 swizzled column offsets (within 256B row)
    int gid, tig, wm, wn;
};

// A: 128 rows x 16 16B-segs = 2048 segs (4/thread); B: 48 x 16 = 768 segs
__device__ __forceinline__ void load_stage(uint32_t sb, int buf,
                                           const __half* __restrict__ A,
                                           const __half* __restrict__ W,
                                           int j0, int k0, int tid) {
    uint32_t sbuf = sb + (uint32_t)buf * STAGE_BYTES;
#pragma unroll
    for (int it = 0; it < 4; it++) {
        int seg = tid + it*NTHREADS;
        int r = seg >> 4, s = seg & 15;
        uint32_t off = (uint32_t)(r*RB + ((s >> 3) << 7) + (((s & 7) ^ (r & 7)) << 4));
        cpa16(sbuf + off, A + (size_t)r*HDIM + k0 + s*8);
    }
    {
        int seg = tid;
        int r = seg >> 4, s = seg & 15;
        int wrow = (r / NC) * HDIM + j0 + (r % NC);
        uint32_t off = (uint32_t)(r*RB + ((s >> 3) << 7) + (((s & 7) ^ (r & 7)) << 4));
        cpa16(sbuf + A_BYTES + off, W + (size_t)wrow*HDIM + k0 + s*8);
        seg = tid + NTHREADS;
        if (seg < 768) {
            r = seg >> 4; s = seg & 15;
            wrow = (r / NC) * HDIM + j0 + (r % NC);
            off = (uint32_t)(r*RB + ((s >> 3) << 7) + (((s & 7) ^ (r & 7)) << 4));
            cpa16(sbuf + A_BYTES + off, W + (size_t)wrow*HDIM + k0 + s*8);
        }
    }
}

__device__ __forceinline__ void compute_stage(uint32_t sb, int buf, const Ctx& c,
                                              float acc[3][4]) {
    uint32_t stage  = sb + (uint32_t)buf * STAGE_BYTES;
    uint32_t bstage = stage + A_BYTES;
#pragma unroll
    for (int q = 0; q < 8; q++) {
        uint32_t ra[4], rb[4], rb2[2];
        ldsm_x4(ra,  stage + c.offA + c.cq4[q]);
        ldsm_x4(rb,  bstage + c.offB4 + c.cq4[q]);
        ldsm_x2(rb2, bstage + c.offB2 + c.cq2[q]);
        mma16816(acc[0], ra, rb[0],  rb[2]);
        mma16816(acc[1], ra, rb[1],  rb[3]);
        mma16816(acc[2], ra, rb2[0], rb2[1]);
    }
}

// multistage pipelined GEMM over npair K-concatenated (A,W) pairs
__device__ __forceinline__ void gemm_multi(uint32_t sb, const Ctx& c, int j0, int tid,
                                           const __half* A0, const __half* W0,
                                           const __half* A1, const __half* W1,
                                           int npair, float acc[3][4]) {
    const int total = npair * NCHUNK;
#pragma unroll
    for (int s = 0; s < NSTAGE-1; s++) {
        const __half* A = (s < NCHUNK) ? A0 : A1;
        const __half* W = (s < NCHUNK) ? W0 : W1;
        load_stage(sb, s % NSTAGE, A, W, j0, (s % NCHUNK)*KC, tid);
        cp_commit();
    }
#pragma unroll 1
    for (int s = 0; s < total; s++) {
        cp_waitp();
        __syncthreads();
        int ns = s + NSTAGE - 1;
        if (ns < total) {
            const __half* A = (ns < NCHUNK) ? A0 : A1;
            const __half* W = (ns < NCHUNK) ? W0 : W1;
            load_stage(sb, ns % NSTAGE, A, W, j0, (ns % NCHUNK)*KC, tid);
        }
        cp_commit();
        compute_stage(sb, s % NSTAGE, c, acc);
    }
}

__device__ __forceinline__ void store_gates(float* sG, const Ctx& c,
                                            const float acc[3][4]) {
#pragma unroll
    for (int tn = 0; tn < 3; tn++) {
        int row = c.wm*16 + c.gid;
        int n   = c.wn*24 + tn*8 + c.tig*2;
        float* p0 = sG + row*NLOC + n;
        p0[0] = acc[tn][0]; p0[1] = acc[tn][1];
        float* p1 = sG + (row + 8)*NLOC + n;
        p1[0] = acc[tn][2]; p1[1] = acc[tn][3];
    }
}

__device__ __forceinline__ void gridbar(unsigned target) {
    __threadfence();
    __syncthreads();
    if (threadIdx.x == 0) {
        atomicAdd(&g_bar, 1u);
        while (*((volatile unsigned*)&g_bar) < target) { __nanosleep(32); }
    }
    __syncthreads();
}

// ---------------- persistent LSTM kernel -------------------------------------
__global__ void __launch_bounds__(NTHREADS, 1)
lstm_kernel(const float* __restrict__ x,
            const float* __restrict__ Wih0,
            const float* __restrict__ bih0, const float* __restrict__ bhh0,
            const float* __restrict__ bih1, const float* __restrict__ bhh1,
            const float* __restrict__ Wlin, const float* __restrict__ blin,
            float* __restrict__ out) {
    extern __shared__ unsigned char dsm[];
    const int tid = threadIdx.x;
    const int j0  = blockIdx.x * NC;
    const uint32_t sb = (uint32_t)__cvta_generic_to_shared(dsm);
    float* sG  = (float*)(dsm + OFF_GATES);
    float* sWx = (float*)(dsm + OFF_WX);
    float* sB0 = (float*)(dsm + OFF_B0);
    float* sB1 = (float*)(dsm + OFF_B1);

    // ---- per-thread fragment addressing context ----
    Ctx c;
    {
        int lane = tid & 31, warp = tid >> 5;
        c.gid = lane >> 2; c.tig = lane & 3;
        c.wm = warp & 7;   c.wn = warp >> 3;      // 8 x 2 warp grid
        int r16 = lane & 15, hi = lane >> 4, xv = lane & 7;
        c.offA  = (uint32_t)((c.wm*16 + r16) * RB);
        c.offB4 = (uint32_t)((c.wn*24 + r16) * RB);
        c.offB2 = (uint32_t)((c.wn*24 + 16 + (lane & 7)) * RB);
        int hi2 = (lane >> 3) & 1;
#pragma unroll
        for (int q = 0; q < 8; q++) {
            int u4 = 2*q + hi;
            int u2 = 2*q + hi2;
            c.cq4[q] = (uint32_t)(((u4 >> 3) << 7) + (((u4 & 7) ^ xv) << 4));
            c.cq2[q] = (uint32_t)(((u2 >> 3) << 7) + (((u2 & 7) ^ xv) << 4));
        }
    }

    // ---- constants: x-projection slice + fused biases ----
    for (int n = tid; n < NLOC; n += NTHREADS) {
        int grow = (n / NC) * HDIM + j0 + (n % NC);
        sB0[n] = bih0[grow] + bhh0[grow];
        sB1[n] = bih1[grow] + bhh1[grow];
#pragma unroll
        for (int k = 0; k < INDIM; k++) sWx[n*INDIM + k] = Wih0[grow*INDIM + k];
    }

    // ---- zero initial h state (each CTA owns its slice) ----
    for (int e = tid; e < BATCH*NC; e += NTHREADS) {
        int b = e / NC, j = e % NC;
        int idx = b*HDIM + j0 + j;
        g_h0[0][idx] = __float2half_rn(0.0f);
        g_h1[0][idx] = __float2half_rn(0.0f);
    }

    // c-state in registers: thread owns elements e = tid + i*512, i<3
    float cr0[NE], cr1[NE];
#pragma unroll
    for (int i = 0; i < NE; i++) { cr0[i] = 0.0f; cr1[i] = 0.0f; }

    unsigned bc = 0;
    gridbar(++bc * NCTA);

#pragma unroll 1
    for (int t = 0; t < T_STEPS; t++) {
        const int p = t & 1;

        // ================= layer 0: gates = Whh0 * h0[p] =================
        float acc[3][4];
#pragma unroll
        for (int b = 0; b < 3; b++)
#pragma unroll
            for (int d = 0; d < 4; d++) acc[b][d] = 0.0f;

        gemm_multi(sb, c, j0, tid, g_h0[p], g_Whh0, g_h0[p], g_Whh0, 1, acc);
        store_gates(sG, c, acc);
        __syncthreads();

        {
            const float* xt = x + (size_t)t * BATCH * INDIM;
#pragma unroll
            for (int i = 0; i < NE; i++) {
                int e = tid + i*NTHREADS;
                int b = e / NC, j = e % NC;
                float iv = sG[b*NLOC + j]          + sB0[j];
                float fv = sG[b*NLOC + NC + j]     + sB0[NC + j];
                float gv = sG[b*NLOC + 2*NC + j]   + sB0[2*NC + j];
                float ov = sG[b*NLOC + 3*NC + j]   + sB0[3*NC + j];
                const float* xr = xt + b*INDIM;
#pragma unroll
                for (int k = 0; k < INDIM; k++) {
                    float xk = xr[k];
                    iv += xk * sWx[j*INDIM + k];
                    fv += xk * sWx[(NC + j)*INDIM + k];
                    gv += xk * sWx[(2*NC + j)*INDIM + k];
                    ov += xk * sWx[(3*NC + j)*INDIM + k];
                }
                float cn = sigm(fv)*cr0[i] + sigm(iv)*tanh_f(gv);
                cr0[i] = cn;
                g_h0[p ^ 1][(size_t)b*HDIM + j0 + j] = __float2half_rn(sigm(ov)*tanh_f(cn));
            }
        }
        gridbar(++bc * NCTA);     // h0[p^1] visible chip-wide

        // ===== layer 1: gates = Wih1*h0[p^1] + Whh1*h1[p] (fused K=3072) =====
#pragma unroll
        for (int b = 0; b < 3; b++)
#pragma unroll
            for (int d = 0; d < 4; d++) acc[b][d] = 0.0f;

        gemm_multi(sb, c, j0, tid, g_h0[p ^ 1], g_Wih1, g_h1[p], g_Whh1, 2, acc);
        store_gates(sG, c, acc);
        __syncthreads();

        {
            const bool last = (t == T_STEPS - 1);
#pragma unroll
            for (int i = 0; i < NE; i++) {
                int e = tid + i*NTHREADS;
                int b = e / NC, j = e % NC;
                float iv = sG[b*NLOC + j]          + sB1[j];
                float fv = sG[b*NLOC + NC + j]     + sB1[NC + j];
                float gv = sG[b*NLOC + 2*NC + j]   + sB1[2*NC + j];
                float ov = sG[b*NLOC + 3*NC + j]   + sB1[3*NC + j];
                float cn = sigm(fv)*cr1[i] + sigm(iv)*tanh_f(gv);
                cr1[i] = cn;
                float hn = sigm(ov)*tanh_f(cn);
                g_h1[p ^ 1][(size_t)b*HDIM + j0 + j] = __float2half_rn(hn);
                if (last) g_h1f[(size_t)b*HDIM + j0 + j] = hn;
            }
        }
        gridbar(++bc * NCTA);     // h1[p^1] visible chip-wide
    }

    // ================= final linear (CTA 0) =================
    if (blockIdx.x == 0) {
#pragma unroll 1
        for (int e = tid; e < BATCH*OUTDIM; e += NTHREADS) {
            int b = e / OUTDIM, o = e % OUTDIM;
            float s = blin[o];
            const float* hr = g_h1f + (size_t)b*HDIM;
            const float* wr = Wlin + (size_t)o*HDIM;
#pragma unroll 4
            for (int k = 0; k < HDIM; k++) s += hr[k] * wr[k];
            out[b*OUTDIM + o] = s;
        }
    }
}

// ---------------- launch ------------------------------------------------------
extern "C" void kernel_launch(void* const* d_in, const int* in_sizes, int n_in,
                              void* d_out, int out_size) {
    const float* x    = (const float*)d_in[0];
    const float* Wih0 = (const float*)d_in[1];
    const float* Whh0 = (const float*)d_in[2];
    const float* bih0 = (const float*)d_in[3];
    const float* bhh0 = (const float*)d_in[4];
    const float* Wih1 = (const float*)d_in[5];
    const float* Whh1 = (const float*)d_in[6];
    const float* bih1 = (const float*)d_in[7];
    const float* bhh1 = (const float*)d_in[8];
    const float* Wlin = (const float*)d_in[9];
    const float* blin = (const float*)d_in[10];

    cudaFuncSetAttribute(lstm_kernel, cudaFuncAttributeMaxDynamicSharedMemorySize, SMEM_DYN);

    int cblocks = (3*WELEMS + 255) / 256;
    convert_kernel<<<cblocks, 256>>>(Whh0, Wih1, Whh1);
    lstm_kernel<<<NCTA, NTHREADS, SMEM_DYN>>>(x, Wih0, bih0, bhh0, bih1, bhh1,
                                              Wlin, blin, (float*)d_out);
}

// round 8
// speedup vs baseline: 1.1382x; 1.1382x over previous
#include <cuda_runtime.h>
#include <cuda_fp16.h>
#include <stdint.h>

#define T_STEPS 1024
#define BATCH   128
#define INDIM   6
#define HDIM    1536
#define OUTDIM  5
#define WELEMS  (4*HDIM*HDIM)     // 9437184

#define NCTA     128
#define NC       12               // h-columns per CTA
#define NLOC     48               // gate rows per CTA (4*NC)
#define NTHREADS 256

#define KC       128              // halfs per K stage (256 B rows = 2 SW128 atoms)
#define RB       256              // row bytes
#define NCHUNK   (HDIM/KC)        // 12 stages per 1536-K GEMM
#define NSTAGE   3
#define A_BYTES  (128*RB)         // 32768
#define B_BYTES  (NLOC*RB)        // 12288
#define STAGE_BYTES (A_BYTES + B_BYTES)        // 45056
#define OFF_GATES   (NSTAGE*STAGE_BYTES)       // 135168 (float[128*48] = 24576)
#define OFF_WX      (OFF_GATES + 128*NLOC*4)   // 159744
#define OFF_B0      (OFF_WX + NLOC*INDIM*4)
#define OFF_B1      (OFF_B0 + NLOC*4)
#define SMEM_DYN    (OFF_B1 + NLOC*4 + 256)    // ~157.8 KB

// ---------------- device globals ---------------------------------------------
__device__ __align__(128) __half g_Whh0[WELEMS];
__device__ __align__(128) __half g_Wih1[WELEMS];
__device__ __align__(128) __half g_Whh1[WELEMS];
__device__ __align__(128) __half g_h0[2][BATCH*HDIM];
__device__ __align__(128) __half g_h1[2][BATCH*HDIM];
__device__ __align__(128) float  g_h1f[BATCH*HDIM];
__device__ unsigned g_bar0, g_bar1;

// ---------------- weight convert + barrier reset -----------------------------
__global__ void convert_kernel(const float* __restrict__ whh0,
                               const float* __restrict__ wih1,
                               const float* __restrict__ whh1) {
    long i = (long)blockIdx.x * blockDim.x + threadIdx.x;
    if (i == 0) { g_bar0 = 0u; g_bar1 = 0u; }
    if (i < (long)WELEMS)            g_Whh0[i]             = __float2half_rn(whh0[i]);
    else if (i < 2L*WELEMS)          g_Wih1[i - WELEMS]    = __float2half_rn(wih1[i - WELEMS]);
    else if (i < 3L*WELEMS)          g_Whh1[i - 2L*WELEMS] = __float2half_rn(whh1[i - 2L*WELEMS]);
}

// ---------------- PTX helpers -------------------------------------------------
__device__ __forceinline__ void cpa16(uint32_t s, const void* g) {
    asm volatile("cp.async.cg.shared.global [%0], [%1], 16;\n" :: "r"(s), "l"(g) : "memory");
}
__device__ __forceinline__ void cp_commit() { asm volatile("cp.async.commit_group;\n" ::: "memory"); }
__device__ __forceinline__ void cp_waitp()  { asm volatile("cp.async.wait_group %0;\n" :: "n"(NSTAGE-2) : "memory"); }

__device__ __forceinline__ void ldsm_x4(uint32_t* r, uint32_t addr) {
    asm volatile("ldmatrix.sync.aligned.m8n8.x4.shared.b16 {%0,%1,%2,%3}, [%4];\n"
                 : "=r"(r[0]), "=r"(r[1]), "=r"(r[2]), "=r"(r[3]) : "r"(addr));
}
__device__ __forceinline__ void ldsm_x2(uint32_t* r, uint32_t addr) {
    asm volatile("ldmatrix.sync.aligned.m8n8.x2.shared.b16 {%0,%1}, [%2];\n"
                 : "=r"(r[0]), "=r"(r[1]) : "r"(addr));
}
__device__ __forceinline__ void mma16816(float* d, const uint32_t* a, uint32_t b0, uint32_t b1) {
    asm volatile(
        "mma.sync.aligned.m16n8k16.row.col.f32.f16.f16.f32 "
        "{%0,%1,%2,%3}, {%4,%5,%6,%7}, {%8,%9}, {%0,%1,%2,%3};\n"
        : "+f"(d[0]), "+f"(d[1]), "+f"(d[2]), "+f"(d[3])
        : "r"(a[0]), "r"(a[1]), "r"(a[2]), "r"(a[3]), "r"(b0), "r"(b1));
}

__device__ __forceinline__ float sigm(float x)  { return __fdividef(1.0f, 1.0f + __expf(-x)); }
__device__ __forceinline__ float tanh_f(float x){ return __fdividef(2.0f, 1.0f + __expf(-2.0f*x)) - 1.0f; }

// ---------------- chip-wide barrier (arrive / deferred wait) ------------------
__device__ __forceinline__ void bar_arrive(unsigned* bar) {
    __threadfence();
    __syncthreads();
    if (threadIdx.x == 0)
        asm volatile("red.global.gpu.add.u32 [%0], 1;" :: "l"(bar) : "memory");
}
__device__ __forceinline__ void bar_wait(unsigned* bar, unsigned target) {
    if (threadIdx.x == 0) {
        unsigned v;
        do {
            asm volatile("ld.volatile.global.u32 %0, [%1];" : "=r"(v) : "l"(bar));
            if (v >= target) break;
            __nanosleep(64);
        } while (true);
    }
    __syncthreads();
    __threadfence();
}

// ---------------- per-thread precomputed context ------------------------------
struct Ctx {
    uint32_t offA0, offA1;   // A row-base byte offsets (tm=0,1) within a stage
    uint32_t offB4, offB2;   // B row-base byte offsets (x4 tiles, x2 tile)
    uint32_t cq4[8], cq2[8]; // per-k16 swizzled column offsets (within 256B row)
    int gid, tig, wm, wn;
};

// A: 128 rows x 16 16B-segs = 2048 segs (8/thread); B: 48 x 16 = 768 segs (3/thread)
__device__ __forceinline__ void load_stage(uint32_t sb, int buf,
                                           const __half* __restrict__ A,
                                           const __half* __restrict__ W,
                                           int j0, int k0, int tid) {
    uint32_t sbuf = sb + (uint32_t)buf * STAGE_BYTES;
#pragma unroll
    for (int it = 0; it < 8; it++) {
        int seg = tid + it*NTHREADS;
        int r = seg >> 4, s = seg & 15;
        uint32_t off = (uint32_t)(r*RB + ((s >> 3) << 7) + (((s & 7) ^ (r & 7)) << 4));
        cpa16(sbuf + off, A + (size_t)r*HDIM + k0 + s*8);
    }
#pragma unroll
    for (int it = 0; it < 3; it++) {
        int seg = tid + it*NTHREADS;
        if (seg < 768) {
            int r = seg >> 4, s = seg & 15;
            int wrow = (r / NC) * HDIM + j0 + (r % NC);
            uint32_t off = (uint32_t)(r*RB + ((s >> 3) << 7) + (((s & 7) ^ (r & 7)) << 4));
            cpa16(sbuf + A_BYTES + off, W + (size_t)wrow*HDIM + k0 + s*8);
        }
    }
}

__device__ __forceinline__ void compute_stage(uint32_t sb, int buf, const Ctx& c,
                                              float acc[2][3][4]) {
    uint32_t stage  = sb + (uint32_t)buf * STAGE_BYTES;
    uint32_t bstage = stage + A_BYTES;
#pragma unroll
    for (int q = 0; q < 8; q++) {
        uint32_t ra[2][4], rb[4], rb2[2];
        ldsm_x4(ra[0], stage + c.offA0 + c.cq4[q]);
        ldsm_x4(ra[1], stage + c.offA1 + c.cq4[q]);
        ldsm_x4(rb,    bstage + c.offB4 + c.cq4[q]);
        ldsm_x2(rb2,   bstage + c.offB2 + c.cq2[q]);
#pragma unroll
        for (int tm = 0; tm < 2; tm++) {
            mma16816(acc[tm][0], ra[tm], rb[0],  rb[2]);
            mma16816(acc[tm][1], ra[tm], rb[1],  rb[3]);
            mma16816(acc[tm][2], ra[tm], rb2[0], rb2[1]);
        }
    }
}

// one 12-chunk pipelined GEMM (accumulates into acc)
__device__ __forceinline__ void gemm_run(uint32_t sb, const Ctx& c, int j0, int tid,
                                         const __half* __restrict__ A,
                                         const __half* __restrict__ W,
                                         float acc[2][3][4]) {
#pragma unroll
    for (int s = 0; s < NSTAGE-1; s++) {
        load_stage(sb, s, A, W, j0, s*KC, tid);
        cp_commit();
    }
#pragma unroll 1
    for (int s = 0; s < NCHUNK; s++) {
        cp_waitp();
        __syncthreads();
        int ns = s + NSTAGE - 1;
        if (ns < NCHUNK) load_stage(sb, ns % NSTAGE, A, W, j0, ns*KC, tid);
        cp_commit();
        compute_stage(sb, s % NSTAGE, c, acc);
    }
}

__device__ __forceinline__ void store_gates(float* sG, const Ctx& c,
                                            const float acc[2][3][4]) {
#pragma unroll
    for (int tm = 0; tm < 2; tm++)
#pragma unroll
        for (int tn = 0; tn < 3; tn++) {
            int row = c.wm*32 + tm*16 + c.gid;
            int n   = c.wn*24 + tn*8 + c.tig*2;
            float* p0 = sG + row*NLOC + n;
            p0[0] = acc[tm][tn][0]; p0[1] = acc[tm][tn][1];
            float* p1 = sG + (row + 8)*NLOC + n;
            p1[0] = acc[tm][tn][2]; p1[1] = acc[tm][tn][3];
        }
}

// ---------------- persistent LSTM kernel -------------------------------------
__global__ void __launch_bounds__(NTHREADS, 1)
lstm_kernel(const float* __restrict__ x,
            const float* __restrict__ Wih0,
            const float* __restrict__ bih0, const float* __restrict__ bhh0,
            const float* __restrict__ bih1, const float* __restrict__ bhh1,
            const float* __restrict__ Wlin, const float* __restrict__ blin,
            float* __restrict__ out) {
    extern __shared__ unsigned char dsm[];
    const int tid = threadIdx.x;
    const int j0  = blockIdx.x * NC;
    const uint32_t sb = (uint32_t)__cvta_generic_to_shared(dsm);
    float* sG  = (float*)(dsm + OFF_GATES);
    float* sWx = (float*)(dsm + OFF_WX);
    float* sB0 = (float*)(dsm + OFF_B0);
    float* sB1 = (float*)(dsm + OFF_B1);

    // ---- per-thread fragment addressing context ----
    Ctx c;
    {
        int lane = tid & 31, warp = tid >> 5;
        c.gid = lane >> 2; c.tig = lane & 3;
        c.wm = warp & 3;   c.wn = warp >> 2;      // 4 x 2 warp grid (m32 x n24)
        int r16 = lane & 15, hi = lane >> 4, xv = lane & 7;
        c.offA0 = (uint32_t)((c.wm*32 + r16) * RB);
        c.offA1 = c.offA0 + 16*RB;
        c.offB4 = (uint32_t)((c.wn*24 + r16) * RB);
        c.offB2 = (uint32_t)((c.wn*24 + 16 + (lane & 7)) * RB);
        int hi2 = (lane >> 3) & 1;
#pragma unroll
        for (int q = 0; q < 8; q++) {
            int u4 = 2*q + hi;
            int u2 = 2*q + hi2;
            c.cq4[q] = (uint32_t)(((u4 >> 3) << 7) + (((u4 & 7) ^ xv) << 4));
            c.cq2[q] = (uint32_t)(((u2 >> 3) << 7) + (((u2 & 7) ^ xv) << 4));
        }
    }

    // ---- constants: x-projection slice + fused biases ----
    for (int n = tid; n < NLOC; n += NTHREADS) {
        int grow = (n / NC) * HDIM + j0 + (n % NC);
        sB0[n] = bih0[grow] + bhh0[grow];
        sB1[n] = bih1[grow] + bhh1[grow];
#pragma unroll
        for (int k = 0; k < INDIM; k++) sWx[n*INDIM + k] = Wih0[grow*INDIM + k];
    }

    // ---- zero initial h state (each CTA owns its slice) ----
    for (int e = tid; e < BATCH*NC; e += NTHREADS) {
        int b = e / NC, j = e % NC;
        int idx = b*HDIM + j0 + j;
        g_h0[0][idx] = __float2half_rn(0.0f);
        g_h1[0][idx] = __float2half_rn(0.0f);
    }

    // c-state in registers: thread owns elements e = tid + i*256, i<6
    float cr0[6], cr1[6];
#pragma unroll
    for (int i = 0; i < 6; i++) { cr0[i] = 0.0f; cr1[i] = 0.0f; }

    // init arrivals on both barriers; wait for h0 visibility
    bar_arrive(&g_bar0);
    bar_arrive(&g_bar1);
    bar_wait(&g_bar0, NCTA);

#pragma unroll 1
    for (int t = 0; t < T_STEPS; t++) {
        const int p = t & 1;
        float acc[2][3][4];

        // ======== G_A: acc = Whh0 * h0[p]  (h0[p] ready from prior bar0 wait) =====
#pragma unroll
        for (int a = 0; a < 2; a++)
#pragma unroll
            for (int b = 0; b < 3; b++)
#pragma unroll
                for (int d = 0; d < 4; d++) acc[a][b][d] = 0.0f;
        gemm_run(sb, c, j0, tid, g_h0[p], g_Whh0, acc);
        store_gates(sG, c, acc);
        __syncthreads();

        // ---- epilogue 0: h0[t] ----
        {
            const float* xt = x + (size_t)t * BATCH * INDIM;
#pragma unroll
            for (int i = 0; i < 6; i++) {
                int e = tid + i*NTHREADS;
                int b = e / NC, j = e % NC;
                float iv = sG[b*NLOC + j]          + sB0[j];
                float fv = sG[b*NLOC + NC + j]     + sB0[NC + j];
                float gv = sG[b*NLOC + 2*NC + j]   + sB0[2*NC + j];
                float ov = sG[b*NLOC + 3*NC + j]   + sB0[3*NC + j];
                const float* xr = xt + b*INDIM;
#pragma unroll
                for (int k = 0; k < INDIM; k++) {
                    float xk = xr[k];
                    iv += xk * sWx[j*INDIM + k];
                    fv += xk * sWx[(NC + j)*INDIM + k];
                    gv += xk * sWx[(2*NC + j)*INDIM + k];
                    ov += xk * sWx[(3*NC + j)*INDIM + k];
                }
                float cn = sigm(fv)*cr0[i] + sigm(iv)*tanh_f(gv);
                cr0[i] = cn;
                g_h0[p ^ 1][(size_t)b*HDIM + j0 + j] = __float2half_rn(sigm(ov)*tanh_f(cn));
            }
        }
        bar_arrive(&g_bar0);                      // h0[t] published

        // ======== G_C: acc = Whh1 * h1[p]  (wait hidden behind G_A + epi0) =======
        bar_wait(&g_bar1, (unsigned)(NCTA*(t + 1)));   // h1[p] chip-wide
#pragma unroll
        for (int a = 0; a < 2; a++)
#pragma unroll
            for (int b = 0; b < 3; b++)
#pragma unroll
                for (int d = 0; d < 4; d++) acc[a][b][d] = 0.0f;
        gemm_run(sb, c, j0, tid, g_h1[p], g_Whh1, acc);

        // ======== G_D: acc += Wih1 * h0[t]  (wait hidden behind G_C) =============
        bar_wait(&g_bar0, (unsigned)(NCTA*(t + 2)));   // h0[t] chip-wide
        gemm_run(sb, c, j0, tid, g_h0[p ^ 1], g_Wih1, acc);
        store_gates(sG, c, acc);
        __syncthreads();

        // ---- epilogue 1: h1[t] ----
        {
            const bool last = (t == T_STEPS - 1);
#pragma unroll
            for (int i = 0; i < 6; i++) {
                int e = tid + i*NTHREADS;
                int b = e / NC, j = e % NC;
                float iv = sG[b*NLOC + j]          + sB1[j];
                float fv = sG[b*NLOC + NC + j]     + sB1[NC + j];
                float gv = sG[b*NLOC + 2*NC + j]   + sB1[2*NC + j];
                float ov = sG[b*NLOC + 3*NC + j]   + sB1[3*NC + j];
                float cn = sigm(fv)*cr1[i] + sigm(iv)*tanh_f(gv);
                cr1[i] = cn;
                float hn = sigm(ov)*tanh_f(cn);
                g_h1[p ^ 1][(size_t)b*HDIM + j0 + j] = __float2half_rn(hn);
                if (last) g_h1f[(size_t)b*HDIM + j0 + j] = hn;
            }
        }
        bar_arrive(&g_bar1);                      // h1[t] published
    }

    // ================= final linear (CTA 0) =================
    bar_wait(&g_bar1, (unsigned)(NCTA*(T_STEPS + 1)));
    if (blockIdx.x == 0) {
#pragma unroll 1
        for (int e = tid; e < BATCH*OUTDIM; e += NTHREADS) {
            int b = e / OUTDIM, o = e % OUTDIM;
            float s = blin[o];
            const float* hr = g_h1f + (size_t)b*HDIM;
            const float* wr = Wlin + (size_t)o*HDIM;
#pragma unroll 4
            for (int k = 0; k < HDIM; k++) s += hr[k] * wr[k];
            out[b*OUTDIM + o] = s;
        }
    }
}

// ---------------- launch ------------------------------------------------------
extern "C" void kernel_launch(void* const* d_in, const int* in_sizes, int n_in,
                              void* d_out, int out_size) {
    const float* x    = (const float*)d_in[0];
    const float* Wih0 = (const float*)d_in[1];
    const float* Whh0 = (const float*)d_in[2];
    const float* bih0 = (const float*)d_in[3];
    const float* bhh0 = (const float*)d_in[4];
    const float* Wih1 = (const float*)d_in[5];
    const float* Whh1 = (const float*)d_in[6];
    const float* bih1 = (const float*)d_in[7];
    const float* bhh1 = (const float*)d_in[8];
    const float* Wlin = (const float*)d_in[9];
    const float* blin = (const float*)d_in[10];

    cudaFuncSetAttribute(lstm_kernel, cudaFuncAttributeMaxDynamicSharedMemorySize, SMEM_DYN);

    int cblocks = (3*WELEMS + 255) / 256;
    convert_kernel<<<cblocks, 256>>>(Whh0, Wih1, Whh1);
    lstm_kernel<<<NCTA, NTHREADS, SMEM_DYN>>>(x, Wih0, bih0, bhh0, bih1, bhh1,
                                              Wlin, blin, (float*)d_out);
}